// round 11
// baseline (speedup 1.0000x reference)
#include <cuda_runtime.h>
#include <cstdint>

// Problem constants (fixed by the dataset generator).
#define NN   40000
#define EE   640000
#define FIN  128
#define FHID 512
#define FOUT 256

#define SCAN_BLOCKS ((NN + 255) / 256)   // 157

// ---------------- scratch (static device globals; no allocation allowed) ----
__device__ int   g_is64;
__device__ int   g_cnt[NN];
__device__ int   g_bsum[256];            // >= SCAN_BLOCKS
__device__ int   g_rowptr[NN + 1];
__device__ int   g_cursor[NN];
__device__ int   g_col[EE];
__device__ float g_xr  [(size_t)NN * FIN];   // tf32-rounded copy of x   (20 MB)
__device__ float g_aggA[(size_t)NN * FIN];   // mean-aggregated x        (20 MB)
__device__ float g_h   [(size_t)NN * FHID];  // layer-1 output           (82 MB)
__device__ float g_p   [(size_t)NN * FOUT];  // h @ W2l                  (40 MB)
__device__ float g_q   [(size_t)NN * FOUT];  // h @ W2r + b2             (40 MB)
// transposed (and tf32-rounded) weights [N,K]
__device__ float g_Wt1l[FHID * FIN];
__device__ float g_Wt1r[FHID * FIN];
__device__ float g_Wt2lr[2 * FOUT * FHID];   // rows 0-255: W2l^T, 256-511: W2r^T

__device__ __forceinline__ float tf32r(float f) {
    uint32_t u;
    asm("cvt.rna.tf32.f32 %0, %1;" : "=r"(u) : "f"(f));
    return __uint_as_float(u);
}

// ---------------- edge dtype detection + direct readers -----------------------
__global__ void detect_kernel(const int* __restrict__ ei32) {
    if (threadIdx.x == 0 && blockIdx.x == 0) {
        int all0 = 1;
        for (int i = 0; i < 64; i++)
            if (ei32[2 * i + 1] != 0) all0 = 0;
        g_is64 = all0;
    }
}
__device__ __forceinline__ int edge_at(const int* __restrict__ ei, int is64, size_t idx) {
    return is64 ? (int)((const long long*)ei)[idx] : ei[idx];
}

// ---------------- CSR build --------------------------------------------------
__global__ void zero_cnt_kernel() {
    int i = blockIdx.x * blockDim.x + threadIdx.x;
    if (i < NN) g_cnt[i] = 0;
}
__global__ void hist_kernel(const int* __restrict__ ei) {
    int e = blockIdx.x * blockDim.x + threadIdx.x;
    if (e < EE) atomicAdd(&g_cnt[edge_at(ei, g_is64, (size_t)EE + e)], 1);
}

// 3-phase exclusive scan of g_cnt -> g_rowptr/g_cursor
__global__ void scan_phase1() {
    __shared__ int sh[256];
    int b = blockIdx.x, t = threadIdx.x;
    int i = b * 256 + t;
    int v = (i < NN) ? g_cnt[i] : 0;
    sh[t] = v;
    __syncthreads();
    for (int off = 128; off > 0; off >>= 1) {
        if (t < off) sh[t] += sh[t + off];
        __syncthreads();
    }
    if (t == 0) g_bsum[b] = sh[0];
}
__global__ void scan_phase2() {
    __shared__ int sh[256];
    int t = threadIdx.x;
    int v = (t < SCAN_BLOCKS) ? g_bsum[t] : 0;
    sh[t] = v;
    __syncthreads();
    for (int off = 1; off < 256; off <<= 1) {
        int u = (t >= off) ? sh[t - off] : 0;
        __syncthreads();
        sh[t] += u;
        __syncthreads();
    }
    g_bsum[t] = sh[t] - v;  // exclusive prefix of block sums
}
__global__ void scan_phase3() {
    __shared__ int sh[256];
    int b = blockIdx.x, t = threadIdx.x;
    int i = b * 256 + t;
    int v = (i < NN) ? g_cnt[i] : 0;
    sh[t] = v;
    __syncthreads();
    for (int off = 1; off < 256; off <<= 1) {
        int u = (t >= off) ? sh[t - off] : 0;
        __syncthreads();
        sh[t] += u;
        __syncthreads();
    }
    int excl = sh[t] - v + g_bsum[b];
    if (i < NN) {
        g_rowptr[i] = excl;
        g_cursor[i] = excl;
    }
    if (b == 0 && t == 0) g_rowptr[NN] = EE;
}

__global__ void fill_kernel(const int* __restrict__ ei) {
    int e = blockIdx.x * blockDim.x + threadIdx.x;
    if (e < EE) {
        int is64 = g_is64;
        int d = edge_at(ei, is64, (size_t)EE + e);
        int s = edge_at(ei, is64, (size_t)e);
        int pos = atomicAdd(&g_cursor[d], 1);
        g_col[pos] = s;
    }
}

// ---------------- fused weight prep: transpose + tf32 round -------------------
#define W1_ELEMS (FIN * FHID)
#define W2_ELEMS (FHID * FOUT)
__global__ void prep_weights(const float* __restrict__ W1l, const float* __restrict__ W1r,
                             const float* __restrict__ W2l, const float* __restrict__ W2r) {
    int idx = blockIdx.x * blockDim.x + threadIdx.x;
    if (idx < W1_ELEMS) {
        int k = idx / FHID, n = idx % FHID;
        g_Wt1l[(size_t)n * FIN + k] = tf32r(W1l[idx]);
        return;
    }
    idx -= W1_ELEMS;
    if (idx < W1_ELEMS) {
        int k = idx / FHID, n = idx % FHID;
        g_Wt1r[(size_t)n * FIN + k] = tf32r(W1r[idx]);
        return;
    }
    idx -= W1_ELEMS;
    if (idx < W2_ELEMS) {
        int k = idx / FOUT, n = idx % FOUT;
        g_Wt2lr[(size_t)n * FHID + k] = tf32r(W2l[idx]);
        return;
    }
    idx -= W2_ELEMS;
    if (idx < W2_ELEMS) {
        int k = idx / FOUT, n = idx % FOUT;
        g_Wt2lr[(size_t)(n + FOUT) * FHID + k] = tf32r(W2r[idx]);
    }
}
#define PREP_TOT (2 * W1_ELEMS + 2 * W2_ELEMS)

// ---------------- layer-1 aggregation (warp per node, fp32 gather) ------------
// Also writes the tf32-rounded copy of this node's own x row into xr.
__global__ void __launch_bounds__(256)
agg1_kernel(const float* __restrict__ x, float* __restrict__ aggA,
            float* __restrict__ xr) {
    int node = blockIdx.x * (blockDim.x >> 5) + (threadIdx.x >> 5);
    if (node >= NN) return;
    int lane = threadIdx.x & 31;
    int beg = g_rowptr[node];
    int end = g_rowptr[node + 1];

    const float4* fb = (const float4*)x;   // row = 32 float4
    float4 acc = make_float4(0.f, 0.f, 0.f, 0.f);

    int j = beg;
    for (; j + 3 < end; j += 4) {
        int s0 = __ldg(&g_col[j + 0]);
        int s1 = __ldg(&g_col[j + 1]);
        int s2 = __ldg(&g_col[j + 2]);
        int s3 = __ldg(&g_col[j + 3]);
        float4 a0 = fb[(size_t)s0 * 32 + lane];
        float4 a1 = fb[(size_t)s1 * 32 + lane];
        float4 a2 = fb[(size_t)s2 * 32 + lane];
        float4 a3 = fb[(size_t)s3 * 32 + lane];
        acc.x += (a0.x + a1.x) + (a2.x + a3.x);
        acc.y += (a0.y + a1.y) + (a2.y + a3.y);
        acc.z += (a0.z + a1.z) + (a2.z + a3.z);
        acc.w += (a0.w + a1.w) + (a2.w + a3.w);
    }
    for (; j < end; j++) {
        int s0 = __ldg(&g_col[j]);
        float4 a = fb[(size_t)s0 * 32 + lane];
        acc.x += a.x; acc.y += a.y; acc.z += a.z; acc.w += a.w;
    }
    float inv = 1.0f / (float)max(end - beg, 1);
    acc.x = tf32r(acc.x * inv); acc.y = tf32r(acc.y * inv);
    acc.z = tf32r(acc.z * inv); acc.w = tf32r(acc.w * inv);
    ((float4*)aggA)[(size_t)node * 32 + lane] = acc;

    float4 v = fb[(size_t)node * 32 + lane];
    v.x = tf32r(v.x); v.y = tf32r(v.y); v.z = tf32r(v.z); v.w = tf32r(v.w);
    ((float4*)xr)[(size_t)node * 32 + lane] = v;
}

// ---------------- layer-2 aggregation (warp per node, fp32, +q residual) ------
__global__ void __launch_bounds__(256)
agg2_kernel(const float* __restrict__ p, const float* __restrict__ q,
            float* __restrict__ out) {
    int node = blockIdx.x * (blockDim.x >> 5) + (threadIdx.x >> 5);
    if (node >= NN) return;
    int lane = threadIdx.x & 31;
    int beg = g_rowptr[node];
    int end = g_rowptr[node + 1];

    const float4* fb = (const float4*)p;   // row = 64 float4
    float4 acc0 = make_float4(0.f, 0.f, 0.f, 0.f);
    float4 acc1 = make_float4(0.f, 0.f, 0.f, 0.f);

    int j = beg;
    for (; j + 3 < end; j += 4) {
        int s0 = __ldg(&g_col[j + 0]);
        int s1 = __ldg(&g_col[j + 1]);
        int s2 = __ldg(&g_col[j + 2]);
        int s3 = __ldg(&g_col[j + 3]);
        const float4* r0 = fb + (size_t)s0 * 64;
        const float4* r1 = fb + (size_t)s1 * 64;
        const float4* r2 = fb + (size_t)s2 * 64;
        const float4* r3 = fb + (size_t)s3 * 64;
        float4 a0 = r0[lane],      b0 = r1[lane],      c0 = r2[lane],      d0 = r3[lane];
        float4 a1 = r0[lane + 32], b1 = r1[lane + 32], c1 = r2[lane + 32], d1 = r3[lane + 32];
        acc0.x += (a0.x + b0.x) + (c0.x + d0.x);
        acc0.y += (a0.y + b0.y) + (c0.y + d0.y);
        acc0.z += (a0.z + b0.z) + (c0.z + d0.z);
        acc0.w += (a0.w + b0.w) + (c0.w + d0.w);
        acc1.x += (a1.x + b1.x) + (c1.x + d1.x);
        acc1.y += (a1.y + b1.y) + (c1.y + d1.y);
        acc1.z += (a1.z + b1.z) + (c1.z + d1.z);
        acc1.w += (a1.w + b1.w) + (c1.w + d1.w);
    }
    for (; j < end; j++) {
        int s0 = __ldg(&g_col[j]);
        const float4* r0 = fb + (size_t)s0 * 64;
        float4 a0 = r0[lane], a1 = r0[lane + 32];
        acc0.x += a0.x; acc0.y += a0.y; acc0.z += a0.z; acc0.w += a0.w;
        acc1.x += a1.x; acc1.y += a1.y; acc1.z += a1.z; acc1.w += a1.w;
    }
    float inv = 1.0f / (float)max(end - beg, 1);
    const float4* qv = (const float4*)(q + (size_t)node * FOUT);
    float4* ov = (float4*)(out + (size_t)node * FOUT);
    float4 q0 = qv[lane], q1 = qv[lane + 32];
    float4 o0, o1;
    o0.x = acc0.x * inv + q0.x; o0.y = acc0.y * inv + q0.y;
    o0.z = acc0.z * inv + q0.z; o0.w = acc0.w * inv + q0.w;
    o1.x = acc1.x * inv + q1.x; o1.y = acc1.y * inv + q1.y;
    o1.z = acc1.z * inv + q1.z; o1.w = acc1.w * inv + q1.w;
    ov[lane]      = o0;
    ov[lane + 32] = o1;
}

// ================= tf32 mma.sync GEMM with ldmatrix fragments ================
// Operands PRE-ROUNDED to tf32 in gmem. Fragments loaded via ldmatrix.x4.b16:
// for 32-bit data an 8x8 b16 matrix = 8 rows x 4 tf32, lane L -> (L>>2, L&3),
// exactly the mma.m16n8k8 fragment distribution -> values are bit-identical
// to the scalar LDS path, at 1/4 the shared-load instruction count.
#define G_BM 128
#define G_BN 128
#define G_BK 32
#define G_PAD_STRIDE 36                     // floats; 144B rows -> LDSM conflict-free
#define G_STAGE_FLOATS (128 * G_PAD_STRIDE)
#define G_STAGE_BYTES (G_STAGE_FLOATS * 4)
#define G_SMEM_SZ (4 * G_STAGE_BYTES)

__device__ __forceinline__ uint32_t smem_u32(const void* p) {
    uint32_t a;
    asm("{ .reg .u64 t; cvta.to.shared.u64 t, %1; cvt.u32.u64 %0, t; }"
        : "=r"(a) : "l"(p));
    return a;
}
__device__ __forceinline__ void cp_async16(uint32_t dst, const void* src, int src_bytes) {
    asm volatile("cp.async.ca.shared.global [%0], [%1], 16, %2;"
                 :: "r"(dst), "l"(src), "r"(src_bytes) : "memory");
}
__device__ __forceinline__ void cp_commit() {
    asm volatile("cp.async.commit_group;" ::: "memory");
}
template <int NPEND>
__device__ __forceinline__ void cp_wait() {
    asm volatile("cp.async.wait_group %0;" :: "n"(NPEND) : "memory");
}
__device__ __forceinline__ void mma_tf32(float* d, const uint32_t* a, const uint32_t* b) {
    asm volatile(
        "mma.sync.aligned.m16n8k8.row.col.f32.tf32.tf32.f32 "
        "{%0,%1,%2,%3}, {%4,%5,%6,%7}, {%8,%9}, {%0,%1,%2,%3};"
        : "+f"(d[0]), "+f"(d[1]), "+f"(d[2]), "+f"(d[3])
        : "r"(a[0]), "r"(a[1]), "r"(a[2]), "r"(a[3]), "r"(b[0]), "r"(b[1]));
}
__device__ __forceinline__ void ldsm_x4(uint32_t& d0, uint32_t& d1, uint32_t& d2,
                                        uint32_t& d3, uint32_t addr) {
    asm volatile("ldmatrix.sync.aligned.m8n8.x4.shared.b16 {%0,%1,%2,%3}, [%4];"
                 : "=r"(d0), "=r"(d1), "=r"(d2), "=r"(d3) : "r"(addr));
}

__device__ __forceinline__ void gemm_issue_tile(
    const float* __restrict__ src, int row0, int row_lim, int K, int k0,
    uint32_t dst_base, int tid) {
#pragma unroll
    for (int u = 0; u < 4; u++) {
        int id  = u * 256 + tid;
        int row = id >> 3;
        int c   = id & 7;
        int gr  = row0 + row;
        int ok  = gr < row_lim;
        const float* s = src + (size_t)(ok ? gr : (row_lim - 1)) * K + k0 + c * 4;
        cp_async16(dst_base + row * (G_PAD_STRIDE * 4) + c * 16, s, ok ? 16 : 0);
    }
}

// split_n == 0: C[M,N] fp32 with optional bias/relu/round_out.
// split_n  > 0: cols < split_n -> C (no bias), cols >= split_n -> C2 (+bias).
__global__ void __launch_bounds__(256)
gemm_tf32_kernel(const float* __restrict__ A1, const float* __restrict__ B1t, int K1,
                 const float* __restrict__ A2, const float* __restrict__ B2t, int K2,
                 const float* __restrict__ bias,
                 float* __restrict__ C, float* __restrict__ C2,
                 int M, int N, int relu, int round_out, int split_n) {
    extern __shared__ float smem[];
    uint32_t sb = smem_u32(smem);

    int tid  = threadIdx.x;
    int lane = tid & 31;
    int wid  = tid >> 5;
    int wm   = wid & 3;
    int wn   = wid >> 2;
    int m0 = blockIdx.y * G_BM;
    int n0 = blockIdx.x * G_BN;

    const int kt1 = K1 >> 5;
    const int KT  = kt1 + (K2 >> 5);

    float acc[2][8][4];
#pragma unroll
    for (int i = 0; i < 2; i++)
#pragma unroll
        for (int j = 0; j < 8; j++)
#pragma unroll
            for (int q = 0; q < 4; q++) acc[i][j][q] = 0.f;

    auto issue = [&](int kt) {
        const float* A;
        const float* B;
        int K, kk;
        if (kt < kt1) { A = A1; B = B1t; K = K1; kk = kt; }
        else          { A = A2; B = B2t; K = K2; kk = kt - kt1; }
        int s = kt & 1;
        uint32_t aB = sb + (uint32_t)(s * 2 * G_STAGE_BYTES);
        uint32_t bB = aB + G_STAGE_BYTES;
        gemm_issue_tile(A, m0, M, K, kk * G_BK, aB, tid);
        gemm_issue_tile(B, n0, N, K, kk * G_BK, bB, tid);
    };

    issue(0);
    cp_commit();

    // ldmatrix per-lane byte offsets within a stage (A and B operand tiles)
    // A (x4 for tm): groups of 8 lanes -> matrices (r,k),(r+8,k),(r,k+4),(r+8,k+4)
    int lrow  = lane & 7;
    int arow0 = wm * 32 + ((lane & 8) ? 8 : 0) + lrow;   // + tm*16
    int acol  = (lane & 16) ? 4 : 0;
    uint32_t offA0 = (uint32_t)((arow0)      * G_PAD_STRIDE + acol) * 4;
    uint32_t offA1 = (uint32_t)((arow0 + 16) * G_PAD_STRIDE + acol) * 4;
    // B (x4 for tn pair): matrices (n,k),(n,k+4),(n+8,k),(n+8,k+4)
    int brow0 = wn * 64 + ((lane & 16) ? 8 : 0) + lrow;  // + tnp*16
    int bcol  = (lane & 8) ? 4 : 0;
    uint32_t offB[4];
#pragma unroll
    for (int tnp = 0; tnp < 4; tnp++)
        offB[tnp] = (uint32_t)((brow0 + tnp * 16) * G_PAD_STRIDE + bcol) * 4;

    int r_lo = (lane >> 2);
    int k_lo = (lane & 3);

    for (int kt = 0; kt < KT; kt++) {
        if (kt + 1 < KT) {
            issue(kt + 1);
            cp_commit();
            cp_wait<1>();
        } else {
            cp_wait<0>();
        }
        __syncthreads();

        int s = kt & 1;
        uint32_t aBase = sb + (uint32_t)(s * 2 * G_STAGE_BYTES);
        uint32_t bBase = aBase + G_STAGE_BYTES;

#pragma unroll
        for (int ks = 0; ks < 4; ks++) {
            uint32_t kb = (uint32_t)(ks * 8 * 4);   // 8 floats per ks step
            uint32_t af[2][4];
            ldsm_x4(af[0][0], af[0][1], af[0][2], af[0][3], aBase + offA0 + kb);
            ldsm_x4(af[1][0], af[1][1], af[1][2], af[1][3], aBase + offA1 + kb);
            uint32_t bf[8][2];
#pragma unroll
            for (int tnp = 0; tnp < 4; tnp++)
                ldsm_x4(bf[2 * tnp][0], bf[2 * tnp][1],
                        bf[2 * tnp + 1][0], bf[2 * tnp + 1][1],
                        bBase + offB[tnp] + kb);
#pragma unroll
            for (int tm = 0; tm < 2; tm++)
#pragma unroll
                for (int tn = 0; tn < 8; tn++)
                    mma_tf32(acc[tm][tn], af[tm], bf[tn]);
        }
        __syncthreads();
    }

    // epilogue
#pragma unroll
    for (int tm = 0; tm < 2; tm++) {
#pragma unroll
        for (int half = 0; half < 2; half++) {
            int m = m0 + wm * 32 + tm * 16 + half * 8 + r_lo;
            if (m >= M) continue;
#pragma unroll
            for (int tn = 0; tn < 8; tn++) {
                int n = n0 + wn * 64 + tn * 8 + k_lo * 2;
                float2 o;
                o.x = acc[tm][tn][half * 2 + 0];
                o.y = acc[tm][tn][half * 2 + 1];
                if (split_n) {
                    if (n < split_n) {
                        *(float2*)(C + (size_t)m * split_n + n) = o;
                    } else {
                        int n2 = n - split_n;
                        float2 bb = *(const float2*)(bias + n2);
                        o.x += bb.x; o.y += bb.y;
                        *(float2*)(C2 + (size_t)m * split_n + n2) = o;
                    }
                    continue;
                }
                if (bias) {
                    float2 bv = *(const float2*)(bias + n);
                    o.x += bv.x; o.y += bv.y;
                }
                if (relu) {
                    o.x = fmaxf(o.x, 0.f);
                    o.y = fmaxf(o.y, 0.f);
                }
                if (round_out) {
                    o.x = tf32r(o.x);
                    o.y = tf32r(o.y);
                }
                *(float2*)(C + (size_t)m * N + n) = o;
            }
        }
    }
}

// ---------------- launcher -----------------------------------------------------
extern "C" void kernel_launch(void* const* d_in, const int* in_sizes, int n_in,
                              void* d_out, int out_size) {
    const float* x   = (const float*)d_in[0];
    const int*   ei  = (const int*)d_in[1];   // int32 OR int64 (device-detected)
    const float* W1l = (const float*)d_in[2];
    const float* b1  = (const float*)d_in[3];
    const float* W1r = (const float*)d_in[4];
    const float* W2l = (const float*)d_in[5];
    const float* b2  = (const float*)d_in[6];
    const float* W2r = (const float*)d_in[7];
    float* out = (float*)d_out;

    float *xr, *aggA, *h, *p, *q, *Wt1l, *Wt1r, *Wt2lr;
    cudaGetSymbolAddress((void**)&xr,    g_xr);
    cudaGetSymbolAddress((void**)&aggA,  g_aggA);
    cudaGetSymbolAddress((void**)&h,     g_h);
    cudaGetSymbolAddress((void**)&p,     g_p);
    cudaGetSymbolAddress((void**)&q,     g_q);
    cudaGetSymbolAddress((void**)&Wt1l,  g_Wt1l);
    cudaGetSymbolAddress((void**)&Wt1r,  g_Wt1r);
    cudaGetSymbolAddress((void**)&Wt2lr, g_Wt2lr);

    static int smem_set = 0;
    if (!smem_set) {
        cudaFuncSetAttribute(gemm_tf32_kernel,
                             cudaFuncAttributeMaxDynamicSharedMemorySize, G_SMEM_SZ);
        smem_set = 1;
    }

    // Edge dtype detection, CSR build (multi-block scan)
    detect_kernel<<<1, 32>>>(ei);
    zero_cnt_kernel<<<(NN + 255) / 256, 256>>>();
    hist_kernel<<<(EE + 255) / 256, 256>>>(ei);
    scan_phase1<<<SCAN_BLOCKS, 256>>>();
    scan_phase2<<<1, 256>>>();
    scan_phase3<<<SCAN_BLOCKS, 256>>>();
    fill_kernel<<<(EE + 255) / 256, 256>>>(ei);

    // Pre-rounded weights
    prep_weights<<<(PREP_TOT + 255) / 256, 256>>>(W1l, W1r, W2l, W2r);

    // Layer 1: aggregate x (+ fused x rounding), h = relu(aggA@W1l + xr@W1r + b1)
    agg1_kernel<<<(NN + 7) / 8, 256>>>(x, aggA, xr);
    {
        dim3 grid(FHID / G_BN, (NN + G_BM - 1) / G_BM);
        gemm_tf32_kernel<<<grid, 256, G_SMEM_SZ>>>(
            aggA, Wt1l, FIN, xr, Wt1r, FIN, b1, h, nullptr,
            NN, FHID, 1, 1, 0);
    }
    // Layer 2 fused GEMM: cols 0-255 -> p = h@W2l, cols 256-511 -> q = h@W2r + b2
    {
        dim3 grid((2 * FOUT) / G_BN, (NN + G_BM - 1) / G_BM);
        gemm_tf32_kernel<<<grid, 256, G_SMEM_SZ>>>(
            h, Wt2lr, FHID, nullptr, nullptr, 0, b2, p, q,
            NN, 2 * FOUT, 0, 0, FOUT);
    }
    // out = scatter_mean(p) + q
    agg2_kernel<<<(NN + 7) / 8, 256>>>(p, q, out);
}

// round 12
// speedup vs baseline: 1.0306x; 1.0306x over previous
#include <cuda_runtime.h>
#include <cstdint>

// Problem constants (fixed by the dataset generator).
#define NN   40000
#define EE   640000
#define FIN  128
#define FHID 512
#define FOUT 256

#define SCAN_BLOCKS ((NN + 255) / 256)   // 157

// ---------------- scratch (static device globals; no allocation allowed) ----
__device__ int   g_is64;
__device__ int   g_cnt[NN];
__device__ int   g_bsum[256];            // >= SCAN_BLOCKS
__device__ int   g_rowptr[NN + 1];
__device__ int   g_cursor[NN];
__device__ int   g_col[EE];
__device__ float g_xr  [(size_t)NN * FIN];   // tf32-rounded copy of x   (20 MB)
__device__ float g_aggA[(size_t)NN * FIN];   // mean-aggregated x        (20 MB)
__device__ float g_h   [(size_t)NN * FHID];  // layer-1 output           (82 MB)
__device__ float g_p   [(size_t)NN * FOUT];  // h @ W2l                  (40 MB)
__device__ float g_q   [(size_t)NN * FOUT];  // h @ W2r + b2             (40 MB)
// transposed (and tf32-rounded) weights [N,K]
__device__ float g_Wt1l[FHID * FIN];
__device__ float g_Wt1r[FHID * FIN];
__device__ float g_Wt2lr[2 * FOUT * FHID];   // rows 0-255: W2l^T, 256-511: W2r^T

__device__ __forceinline__ float tf32r(float f) {
    uint32_t u;
    asm("cvt.rna.tf32.f32 %0, %1;" : "=r"(u) : "f"(f));
    return __uint_as_float(u);
}
__device__ __forceinline__ int edge_at(const int* __restrict__ ei, int is64, size_t idx) {
    return is64 ? (int)((const long long*)ei)[idx] : ei[idx];
}

// ---------------- CSR build --------------------------------------------------
// zero_cnt + edge-dtype detection fused (block 0 / thread 0 does detection).
__global__ void zero_cnt_kernel(const int* __restrict__ ei32) {
    int i = blockIdx.x * blockDim.x + threadIdx.x;
    if (i < NN) g_cnt[i] = 0;
    if (i == 0) {
        int all0 = 1;
        for (int k = 0; k < 64; k++)
            if (ei32[2 * k + 1] != 0) all0 = 0;
        g_is64 = all0;
    }
}
__global__ void hist_kernel(const int* __restrict__ ei) {
    int e = blockIdx.x * blockDim.x + threadIdx.x;
    if (e < EE) atomicAdd(&g_cnt[edge_at(ei, g_is64, (size_t)EE + e)], 1);
}

// Phase 1: per-block reduce -> g_bsum
__global__ void scan_phase1() {
    __shared__ int sh[256];
    int b = blockIdx.x, t = threadIdx.x;
    int i = b * 256 + t;
    int v = (i < NN) ? g_cnt[i] : 0;
    sh[t] = v;
    __syncthreads();
    for (int off = 128; off > 0; off >>= 1) {
        if (t < off) sh[t] += sh[t + off];
        __syncthreads();
    }
    if (t == 0) g_bsum[b] = sh[0];
}
// Phase 2+3 fused: every block redundantly scans the 157 block sums (cheap,
// L2-resident), picks its own exclusive offset, then scans its 256 elements.
__global__ void scan_phase23() {
    __shared__ int sb_[256];
    __shared__ int sh[256];
    __shared__ int blockoff;
    int b = blockIdx.x, t = threadIdx.x;

    int bv = (t < SCAN_BLOCKS) ? g_bsum[t] : 0;
    sb_[t] = bv;
    __syncthreads();
    for (int off = 1; off < 256; off <<= 1) {
        int u = (t >= off) ? sb_[t - off] : 0;
        __syncthreads();
        sb_[t] += u;
        __syncthreads();
    }
    if (t == b) blockoff = sb_[t] - bv;   // exclusive prefix of this block
    __syncthreads();

    int i = b * 256 + t;
    int v = (i < NN) ? g_cnt[i] : 0;
    sh[t] = v;
    __syncthreads();
    for (int off = 1; off < 256; off <<= 1) {
        int u = (t >= off) ? sh[t - off] : 0;
        __syncthreads();
        sh[t] += u;
        __syncthreads();
    }
    int excl = sh[t] - v + blockoff;
    if (i < NN) {
        g_rowptr[i] = excl;
        g_cursor[i] = excl;
    }
    if (b == 0 && t == 0) g_rowptr[NN] = EE;
}

__global__ void fill_kernel(const int* __restrict__ ei) {
    int e = blockIdx.x * blockDim.x + threadIdx.x;
    if (e < EE) {
        int is64 = g_is64;
        int d = edge_at(ei, is64, (size_t)EE + e);
        int s = edge_at(ei, is64, (size_t)e);
        int pos = atomicAdd(&g_cursor[d], 1);
        g_col[pos] = s;
    }
}

// ---------------- fused weight prep: transpose + tf32 round -------------------
#define W1_ELEMS (FIN * FHID)
#define W2_ELEMS (FHID * FOUT)
__global__ void prep_weights(const float* __restrict__ W1l, const float* __restrict__ W1r,
                             const float* __restrict__ W2l, const float* __restrict__ W2r) {
    int idx = blockIdx.x * blockDim.x + threadIdx.x;
    if (idx < W1_ELEMS) {
        int k = idx / FHID, n = idx % FHID;
        g_Wt1l[(size_t)n * FIN + k] = tf32r(W1l[idx]);
        return;
    }
    idx -= W1_ELEMS;
    if (idx < W1_ELEMS) {
        int k = idx / FHID, n = idx % FHID;
        g_Wt1r[(size_t)n * FIN + k] = tf32r(W1r[idx]);
        return;
    }
    idx -= W1_ELEMS;
    if (idx < W2_ELEMS) {
        int k = idx / FOUT, n = idx % FOUT;
        g_Wt2lr[(size_t)n * FHID + k] = tf32r(W2l[idx]);
        return;
    }
    idx -= W2_ELEMS;
    if (idx < W2_ELEMS) {
        int k = idx / FOUT, n = idx % FOUT;
        g_Wt2lr[(size_t)(n + FOUT) * FHID + k] = tf32r(W2r[idx]);
    }
}
#define PREP_TOT (2 * W1_ELEMS + 2 * W2_ELEMS)

// ---------------- layer-1 aggregation (warp per node, fp32 gather) ------------
__global__ void __launch_bounds__(256)
agg1_kernel(const float* __restrict__ x, float* __restrict__ aggA,
            float* __restrict__ xr) {
    int node = blockIdx.x * (blockDim.x >> 5) + (threadIdx.x >> 5);
    if (node >= NN) return;
    int lane = threadIdx.x & 31;
    int beg = g_rowptr[node];
    int end = g_rowptr[node + 1];

    const float4* fb = (const float4*)x;   // row = 32 float4
    float4 acc = make_float4(0.f, 0.f, 0.f, 0.f);

    int j = beg;
    for (; j + 3 < end; j += 4) {
        int s0 = __ldg(&g_col[j + 0]);
        int s1 = __ldg(&g_col[j + 1]);
        int s2 = __ldg(&g_col[j + 2]);
        int s3 = __ldg(&g_col[j + 3]);
        float4 a0 = fb[(size_t)s0 * 32 + lane];
        float4 a1 = fb[(size_t)s1 * 32 + lane];
        float4 a2 = fb[(size_t)s2 * 32 + lane];
        float4 a3 = fb[(size_t)s3 * 32 + lane];
        acc.x += (a0.x + a1.x) + (a2.x + a3.x);
        acc.y += (a0.y + a1.y) + (a2.y + a3.y);
        acc.z += (a0.z + a1.z) + (a2.z + a3.z);
        acc.w += (a0.w + a1.w) + (a2.w + a3.w);
    }
    for (; j < end; j++) {
        int s0 = __ldg(&g_col[j]);
        float4 a = fb[(size_t)s0 * 32 + lane];
        acc.x += a.x; acc.y += a.y; acc.z += a.z; acc.w += a.w;
    }
    float inv = 1.0f / (float)max(end - beg, 1);
    acc.x = tf32r(acc.x * inv); acc.y = tf32r(acc.y * inv);
    acc.z = tf32r(acc.z * inv); acc.w = tf32r(acc.w * inv);
    ((float4*)aggA)[(size_t)node * 32 + lane] = acc;

    float4 v = fb[(size_t)node * 32 + lane];
    v.x = tf32r(v.x); v.y = tf32r(v.y); v.z = tf32r(v.z); v.w = tf32r(v.w);
    ((float4*)xr)[(size_t)node * 32 + lane] = v;
}

// ---------------- layer-2 aggregation (warp per node, fp32, +q residual) ------
__global__ void __launch_bounds__(256)
agg2_kernel(const float* __restrict__ p, const float* __restrict__ q,
            float* __restrict__ out) {
    int node = blockIdx.x * (blockDim.x >> 5) + (threadIdx.x >> 5);
    if (node >= NN) return;
    int lane = threadIdx.x & 31;
    int beg = g_rowptr[node];
    int end = g_rowptr[node + 1];

    const float4* fb = (const float4*)p;   // row = 64 float4
    float4 acc0 = make_float4(0.f, 0.f, 0.f, 0.f);
    float4 acc1 = make_float4(0.f, 0.f, 0.f, 0.f);

    int j = beg;
    for (; j + 3 < end; j += 4) {
        int s0 = __ldg(&g_col[j + 0]);
        int s1 = __ldg(&g_col[j + 1]);
        int s2 = __ldg(&g_col[j + 2]);
        int s3 = __ldg(&g_col[j + 3]);
        const float4* r0 = fb + (size_t)s0 * 64;
        const float4* r1 = fb + (size_t)s1 * 64;
        const float4* r2 = fb + (size_t)s2 * 64;
        const float4* r3 = fb + (size_t)s3 * 64;
        float4 a0 = r0[lane],      b0 = r1[lane],      c0 = r2[lane],      d0 = r3[lane];
        float4 a1 = r0[lane + 32], b1 = r1[lane + 32], c1 = r2[lane + 32], d1 = r3[lane + 32];
        acc0.x += (a0.x + b0.x) + (c0.x + d0.x);
        acc0.y += (a0.y + b0.y) + (c0.y + d0.y);
        acc0.z += (a0.z + b0.z) + (c0.z + d0.z);
        acc0.w += (a0.w + b0.w) + (c0.w + d0.w);
        acc1.x += (a1.x + b1.x) + (c1.x + d1.x);
        acc1.y += (a1.y + b1.y) + (c1.y + d1.y);
        acc1.z += (a1.z + b1.z) + (c1.z + d1.z);
        acc1.w += (a1.w + b1.w) + (c1.w + d1.w);
    }
    for (; j < end; j++) {
        int s0 = __ldg(&g_col[j]);
        const float4* r0 = fb + (size_t)s0 * 64;
        float4 a0 = r0[lane], a1 = r0[lane + 32];
        acc0.x += a0.x; acc0.y += a0.y; acc0.z += a0.z; acc0.w += a0.w;
        acc1.x += a1.x; acc1.y += a1.y; acc1.z += a1.z; acc1.w += a1.w;
    }
    float inv = 1.0f / (float)max(end - beg, 1);
    const float4* qv = (const float4*)(q + (size_t)node * FOUT);
    float4* ov = (float4*)(out + (size_t)node * FOUT);
    float4 q0 = qv[lane], q1 = qv[lane + 32];
    float4 o0, o1;
    o0.x = acc0.x * inv + q0.x; o0.y = acc0.y * inv + q0.y;
    o0.z = acc0.z * inv + q0.z; o0.w = acc0.w * inv + q0.w;
    o1.x = acc1.x * inv + q1.x; o1.y = acc1.y * inv + q1.y;
    o1.z = acc1.z * inv + q1.z; o1.w = acc1.w * inv + q1.w;
    ov[lane]      = o0;
    ov[lane + 32] = o1;
}

// ================= tf32 mma.sync GEMM, BM=128 x BN=256, 3-stage ==============
// Operands PRE-ROUNDED to tf32 in gmem; fragments via ldmatrix.x4.b16
// (bit-identical to scalar LDS path). 512 threads = 4x4 warps of 32x64 tiles.
#define G_BM 128
#define G_BN 256
#define G_BK 32
#define G_STAGES 3
#define G_PAD_STRIDE 36                              // floats per smem row
#define G_A_BYTES (G_BM * G_PAD_STRIDE * 4)          // 18432
#define G_B_BYTES (G_BN * G_PAD_STRIDE * 4)          // 36864
#define G_STAGE_BYTES (G_A_BYTES + G_B_BYTES)        // 55296
#define G_SMEM_SZ (G_STAGES * G_STAGE_BYTES)         // 165888

__device__ __forceinline__ uint32_t smem_u32(const void* p) {
    uint32_t a;
    asm("{ .reg .u64 t; cvta.to.shared.u64 t, %1; cvt.u32.u64 %0, t; }"
        : "=r"(a) : "l"(p));
    return a;
}
__device__ __forceinline__ void cp_async16(uint32_t dst, const void* src, int src_bytes) {
    asm volatile("cp.async.ca.shared.global [%0], [%1], 16, %2;"
                 :: "r"(dst), "l"(src), "r"(src_bytes) : "memory");
}
__device__ __forceinline__ void cp_commit() {
    asm volatile("cp.async.commit_group;" ::: "memory");
}
template <int NPEND>
__device__ __forceinline__ void cp_wait() {
    asm volatile("cp.async.wait_group %0;" :: "n"(NPEND) : "memory");
}
__device__ __forceinline__ void mma_tf32(float* d, const uint32_t* a, const uint32_t* b) {
    asm volatile(
        "mma.sync.aligned.m16n8k8.row.col.f32.tf32.tf32.f32 "
        "{%0,%1,%2,%3}, {%4,%5,%6,%7}, {%8,%9}, {%0,%1,%2,%3};"
        : "+f"(d[0]), "+f"(d[1]), "+f"(d[2]), "+f"(d[3])
        : "r"(a[0]), "r"(a[1]), "r"(a[2]), "r"(a[3]), "r"(b[0]), "r"(b[1]));
}
__device__ __forceinline__ void ldsm_x4(uint32_t& d0, uint32_t& d1, uint32_t& d2,
                                        uint32_t& d3, uint32_t addr) {
    asm volatile("ldmatrix.sync.aligned.m8n8.x4.shared.b16 {%0,%1,%2,%3}, [%4];"
                 : "=r"(d0), "=r"(d1), "=r"(d2), "=r"(d3) : "r"(addr));
}

// ROWS x 32-float tile -> smem via cp.async (512 threads).
template <int ROWS>
__device__ __forceinline__ void issue_tile(
    const float* __restrict__ src, int row0, int row_lim, int K, int k0,
    uint32_t dst_base, int tid) {
#pragma unroll
    for (int u = 0; u < (ROWS * 8) / 512; u++) {
        int id  = u * 512 + tid;
        int row = id >> 3;
        int c   = id & 7;
        int gr  = row0 + row;
        int ok  = gr < row_lim;
        const float* s = src + (size_t)(ok ? gr : (row_lim - 1)) * K + k0 + c * 4;
        cp_async16(dst_base + row * (G_PAD_STRIDE * 4) + c * 16, s, ok ? 16 : 0);
    }
}

// split_n == 0: C[M,N] fp32 with optional bias/relu/round_out.
// split_n  > 0: cols < split_n -> C (no bias), cols >= split_n -> C2 (+bias).
__global__ void __launch_bounds__(512, 1)
gemm_tf32_kernel(const float* __restrict__ A1, const float* __restrict__ B1t, int K1,
                 const float* __restrict__ A2, const float* __restrict__ B2t, int K2,
                 const float* __restrict__ bias,
                 float* __restrict__ C, float* __restrict__ C2,
                 int M, int N, int relu, int round_out, int split_n) {
    extern __shared__ float smem[];
    uint32_t sb = smem_u32(smem);

    int tid  = threadIdx.x;
    int lane = tid & 31;
    int wid  = tid >> 5;        // 0..15
    int wm   = wid & 3;         // 4 row groups x 32 = 128
    int wn   = wid >> 2;        // 4 col groups x 64 = 256
    int m0 = blockIdx.y * G_BM;
    int n0 = blockIdx.x * G_BN;

    const int kt1 = K1 >> 5;
    const int KT  = kt1 + (K2 >> 5);

    float acc[2][8][4];
#pragma unroll
    for (int i = 0; i < 2; i++)
#pragma unroll
        for (int j = 0; j < 8; j++)
#pragma unroll
            for (int q = 0; q < 4; q++) acc[i][j][q] = 0.f;

    auto issue = [&](int kt) {
        const float* A;
        const float* B;
        int K, kk;
        if (kt < kt1) { A = A1; B = B1t; K = K1; kk = kt; }
        else          { A = A2; B = B2t; K = K2; kk = kt - kt1; }
        int s = kt % G_STAGES;
        uint32_t aB = sb + (uint32_t)(s * G_STAGE_BYTES);
        uint32_t bB = aB + G_A_BYTES;
        issue_tile<G_BM>(A, m0, M, K, kk * G_BK, aB, tid);
        issue_tile<G_BN>(B, n0, N, K, kk * G_BK, bB, tid);
    };

    // prologue: stages 0 and 1 in flight
    issue(0);
    cp_commit();
    issue(1);
    cp_commit();

    // ldmatrix per-lane byte offsets (within a stage)
    int lrow  = lane & 7;
    int arow0 = wm * 32 + ((lane & 8) ? 8 : 0) + lrow;   // + tm*16
    int acol  = (lane & 16) ? 4 : 0;
    uint32_t offA0 = (uint32_t)((arow0)      * G_PAD_STRIDE + acol) * 4;
    uint32_t offA1 = (uint32_t)((arow0 + 16) * G_PAD_STRIDE + acol) * 4;
    int brow0 = wn * 64 + ((lane & 16) ? 8 : 0) + lrow;  // + tnp*16
    int bcol  = (lane & 8) ? 4 : 0;
    uint32_t offB[4];
#pragma unroll
    for (int tnp = 0; tnp < 4; tnp++)
        offB[tnp] = (uint32_t)((brow0 + tnp * 16) * G_PAD_STRIDE + bcol) * 4;

    int r_lo = (lane >> 2);
    int k_lo = (lane & 3);

    for (int kt = 0; kt < KT; kt++) {
        if (kt + 1 < KT) cp_wait<1>();
        else             cp_wait<0>();
        __syncthreads();   // stage kt ready; all warps done computing kt-1

        if (kt + 2 < KT) {
            issue(kt + 2);
            cp_commit();
        }

        int s = kt % G_STAGES;
        uint32_t aBase = sb + (uint32_t)(s * G_STAGE_BYTES);
        uint32_t bBase = aBase + G_A_BYTES;

#pragma unroll
        for (int ks = 0; ks < 4; ks++) {
            uint32_t kb = (uint32_t)(ks * 8 * 4);
            uint32_t af[2][4];
            ldsm_x4(af[0][0], af[0][1], af[0][2], af[0][3], aBase + offA0 + kb);
            ldsm_x4(af[1][0], af[1][1], af[1][2], af[1][3], aBase + offA1 + kb);
            uint32_t bf[8][2];
#pragma unroll
            for (int tnp = 0; tnp < 4; tnp++)
                ldsm_x4(bf[2 * tnp][0], bf[2 * tnp][1],
                        bf[2 * tnp + 1][0], bf[2 * tnp + 1][1],
                        bBase + offB[tnp] + kb);
#pragma unroll
            for (int tm = 0; tm < 2; tm++)
#pragma unroll
                for (int tn = 0; tn < 8; tn++)
                    mma_tf32(acc[tm][tn], af[tm], bf[tn]);
        }
    }

    // epilogue
#pragma unroll
    for (int tm = 0; tm < 2; tm++) {
#pragma unroll
        for (int half = 0; half < 2; half++) {
            int m = m0 + wm * 32 + tm * 16 + half * 8 + r_lo;
            if (m >= M) continue;
#pragma unroll
            for (int tn = 0; tn < 8; tn++) {
                int n = n0 + wn * 64 + tn * 8 + k_lo * 2;
                float2 o;
                o.x = acc[tm][tn][half * 2 + 0];
                o.y = acc[tm][tn][half * 2 + 1];
                if (split_n) {
                    if (n < split_n) {
                        *(float2*)(C + (size_t)m * split_n + n) = o;
                    } else {
                        int n2 = n - split_n;
                        float2 bb = *(const float2*)(bias + n2);
                        o.x += bb.x; o.y += bb.y;
                        *(float2*)(C2 + (size_t)m * split_n + n2) = o;
                    }
                    continue;
                }
                if (bias) {
                    float2 bv = *(const float2*)(bias + n);
                    o.x += bv.x; o.y += bv.y;
                }
                if (relu) {
                    o.x = fmaxf(o.x, 0.f);
                    o.y = fmaxf(o.y, 0.f);
                }
                if (round_out) {
                    o.x = tf32r(o.x);
                    o.y = tf32r(o.y);
                }
                *(float2*)(C + (size_t)m * N + n) = o;
            }
        }
    }
}

// ---------------- launcher -----------------------------------------------------
extern "C" void kernel_launch(void* const* d_in, const int* in_sizes, int n_in,
                              void* d_out, int out_size) {
    const float* x   = (const float*)d_in[0];
    const int*   ei  = (const int*)d_in[1];   // int32 OR int64 (device-detected)
    const float* W1l = (const float*)d_in[2];
    const float* b1  = (const float*)d_in[3];
    const float* W1r = (const float*)d_in[4];
    const float* W2l = (const float*)d_in[5];
    const float* b2  = (const float*)d_in[6];
    const float* W2r = (const float*)d_in[7];
    float* out = (float*)d_out;

    float *xr, *aggA, *h, *p, *q, *Wt1l, *Wt1r, *Wt2lr;
    cudaGetSymbolAddress((void**)&xr,    g_xr);
    cudaGetSymbolAddress((void**)&aggA,  g_aggA);
    cudaGetSymbolAddress((void**)&h,     g_h);
    cudaGetSymbolAddress((void**)&p,     g_p);
    cudaGetSymbolAddress((void**)&q,     g_q);
    cudaGetSymbolAddress((void**)&Wt1l,  g_Wt1l);
    cudaGetSymbolAddress((void**)&Wt1r,  g_Wt1r);
    cudaGetSymbolAddress((void**)&Wt2lr, g_Wt2lr);

    static int smem_set = 0;
    if (!smem_set) {
        cudaFuncSetAttribute(gemm_tf32_kernel,
                             cudaFuncAttributeMaxDynamicSharedMemorySize, G_SMEM_SZ);
        smem_set = 1;
    }

    // CSR build (launch order puts agg1 at index 5 -> ncu sample lands on it)
    zero_cnt_kernel<<<(NN + 255) / 256, 256>>>(ei);      // 0 (+dtype detect)
    hist_kernel<<<(EE + 255) / 256, 256>>>(ei);          // 1
    scan_phase1<<<SCAN_BLOCKS, 256>>>();                 // 2
    scan_phase23<<<SCAN_BLOCKS, 256>>>();                // 3
    fill_kernel<<<(EE + 255) / 256, 256>>>(ei);          // 4

    // Layer 1 aggregation (+ fused x rounding)                 // 5 <- profiled
    agg1_kernel<<<(NN + 7) / 8, 256>>>(x, aggA, xr);

    // Pre-rounded weights                                        // 6
    prep_weights<<<(PREP_TOT + 255) / 256, 256>>>(W1l, W1r, W2l, W2r);

    // Layer 1 GEMM: h = relu(aggA@W1l + xr@W1r + b1), tf32-rounded out  // 7
    {
        dim3 grid(FHID / G_BN, (NN + G_BM - 1) / G_BM);
        gemm_tf32_kernel<<<grid, 512, G_SMEM_SZ>>>(
            aggA, Wt1l, FIN, xr, Wt1r, FIN, b1, h, nullptr,
            NN, FHID, 1, 1, 0);
    }
    // Layer 2 fused GEMM: cols 0-255 -> p = h@W2l, cols 256-511 -> q     // 8
    {
        dim3 grid((2 * FOUT) / G_BN, (NN + G_BM - 1) / G_BM);
        gemm_tf32_kernel<<<grid, 512, G_SMEM_SZ>>>(
            h, Wt2lr, FHID, nullptr, nullptr, 0, b2, p, q,
            NN, 2 * FOUT, 0, 0, FOUT);
    }
    // out = scatter_mean(p) + q                                          // 9
    agg2_kernel<<<(NN + 7) / 8, 256>>>(p, q, out);
}